// round 3
// baseline (speedup 1.0000x reference)
#include <cuda_runtime.h>
#include <cuda_bf16.h>
#include <math.h>

// Problem constants
#define BATCH 4
#define SEQT  1024
#define DMODEL 1024
#define NHEAD 16
#define DHEAD 64
#define NBH   (BATCH*NHEAD)      // 64
#define BT    (BATCH*SEQT)       // 4096
#define NSTEPS 3

// ---------------- scratch (device globals; no allocation allowed) ------------
__device__ float g_Q  [BT*DMODEL];
__device__ float g_K  [BT*DMODEL];
__device__ float g_V  [BT*DMODEL];
__device__ float g_DreA[BT*DMODEL];
__device__ float g_DimA[BT*DMODEL];
__device__ float g_DreB[BT*DMODEL];
__device__ float g_DimB[BT*DMODEL];
__device__ float g_A  [(size_t)NBH*SEQT*SEQT];   // 256 MB adjacency
__device__ float g_P  [BT*DMODEL];               // gated values, (B,T,DM)
__device__ float g_gate_scratch[(size_t)NBH*SEQT*DHEAD]; // fallback gate buffer

// ---------------- generic batched GEMM: C = alpha*A@B(+T) + beta*Cin ---------
// Batch z decomposes as outer=z>>4, inner=z&15 (matches (b,h) with H=16).
// Tiles: 64x64, 256 threads (16x16), 4x4 per thread, K-tile 16.
template<bool TRANSB>
__global__ void gemm_k(const float* __restrict__ A, long sAo, long sAi, int lda,
                       const float* __restrict__ B, long sBo, long sBi, int ldb,
                       const float* __restrict__ Cin, long sIo, long sIi, int ldi,
                       float*       __restrict__ C, long sCo, long sCi, int ldc,
                       int K, float alpha, float beta,
                       const float* __restrict__ lam_ptr)
{
    const int bz = blockIdx.z;
    const long ao = (long)(bz >> 4) * sAo + (long)(bz & 15) * sAi;
    const long bo = (long)(bz >> 4) * sBo + (long)(bz & 15) * sBi;
    const long io = (long)(bz >> 4) * sIo + (long)(bz & 15) * sIi;
    const long co = (long)(bz >> 4) * sCo + (long)(bz & 15) * sCi;

    __shared__ float As[16][65];
    __shared__ float Bs[16][65];

    const int tx = threadIdx.x, ty = threadIdx.y;
    const int tid = ty * 16 + tx;
    const int row0 = blockIdx.y * 64;
    const int col0 = blockIdx.x * 64;

    float acc[4][4];
#pragma unroll
    for (int i = 0; i < 4; i++)
#pragma unroll
        for (int j = 0; j < 4; j++) acc[i][j] = 0.f;

    for (int k0 = 0; k0 < K; k0 += 16) {
        // A tile 64x16
#pragma unroll
        for (int i = 0; i < 4; i++) {
            int e = tid + i * 256;
            int r = e >> 4, c = e & 15;
            As[c][r] = A[ao + (long)(row0 + r) * lda + (k0 + c)];
        }
        // B tile 16x64
        if (TRANSB) {
#pragma unroll
            for (int i = 0; i < 4; i++) {
                int e = tid + i * 256;
                int kk = e & 15, n = e >> 4;
                Bs[kk][n] = B[bo + (long)(col0 + n) * ldb + (k0 + kk)];
            }
        } else {
#pragma unroll
            for (int i = 0; i < 4; i++) {
                int e = tid + i * 256;
                int kk = e >> 6, n = e & 63;
                Bs[kk][n] = B[bo + (long)(k0 + kk) * ldb + (col0 + n)];
            }
        }
        __syncthreads();
#pragma unroll
        for (int kk = 0; kk < 16; kk++) {
            float a[4], b[4];
#pragma unroll
            for (int i = 0; i < 4; i++) a[i] = As[kk][ty * 4 + i];
#pragma unroll
            for (int j = 0; j < 4; j++) b[j] = Bs[kk][tx * 4 + j];
#pragma unroll
            for (int i = 0; i < 4; i++)
#pragma unroll
                for (int j = 0; j < 4; j++) acc[i][j] = fmaf(a[i], b[j], acc[i][j]);
        }
        __syncthreads();
    }

    float al = alpha, be = beta;
    if (lam_ptr) {                       // propagation step: alpha=lam, beta=1-lam
        float lam = 1.f / (1.f + __expf(-*lam_ptr));
        al = lam; be = 1.f - lam;
    }
#pragma unroll
    for (int i = 0; i < 4; i++) {
        int r = row0 + ty * 4 + i;
#pragma unroll
        for (int j = 0; j < 4; j++) {
            int cidx = col0 + tx * 4 + j;
            float v = al * acc[i][j];
            if (Cin) v += be * Cin[io + (long)r * ldi + cidx];
            C[co + (long)r * ldc + cidx] = v;
        }
    }
}

// ---------------- row softmax over last axis (rows of 1024) ------------------
__global__ void softmax_rows_k(float* __restrict__ A)
{
    float* p = A + (long)blockIdx.x * SEQT;
    const int tid = threadIdx.x;
    __shared__ float sh[8];

    float m = -1e30f;
    for (int i = tid; i < SEQT; i += 256) m = fmaxf(m, p[i]);
#pragma unroll
    for (int o = 16; o; o >>= 1) m = fmaxf(m, __shfl_xor_sync(0xffffffffu, m, o));
    if ((tid & 31) == 0) sh[tid >> 5] = m;
    __syncthreads();
    if (tid == 0) {
        float mm = sh[0];
        for (int i = 1; i < 8; i++) mm = fmaxf(mm, sh[i]);
        sh[0] = mm;
    }
    __syncthreads();
    m = sh[0];
    __syncthreads();

    float s = 0.f;
    for (int i = tid; i < SEQT; i += 256) {
        float e = __expf(p[i] - m);
        p[i] = e;
        s += e;
    }
#pragma unroll
    for (int o = 16; o; o >>= 1) s += __shfl_xor_sync(0xffffffffu, s, o);
    if ((tid & 31) == 0) sh[tid >> 5] = s;
    __syncthreads();
    if (tid == 0) {
        float ss = 0.f;
        for (int i = 0; i < 8; i++) ss += sh[i];
        sh[0] = ss;
    }
    __syncthreads();
    float inv = 1.f / sh[0];
    for (int i = tid; i < SEQT; i += 256) p[i] *= inv;
}

// ---------------- readout: mean field, cosine, softmax over T, gate*V --------
// block = one (b,h); blockDim = (64, 8)
__global__ void readout_k(const float* __restrict__ Dre, const float* __restrict__ Dim,
                          const float* __restrict__ V,
                          float* __restrict__ gate, float* __restrict__ outp)
{
    const int bh = blockIdx.x;
    const int b = bh >> 4, h = bh & 15;
    const int d = threadIdx.x;     // 0..63
    const int ty = threadIdx.y;    // 0..7
    const long rowbase = (long)b * SEQT * DMODEL + h * DHEAD + d;  // + t*DMODEL

    __shared__ float red[8][64], red2[8][64];
    __shared__ float mre[64], mim[64], stat[64];

    // mean over T
    float sre = 0.f, sim = 0.f;
    for (int t = ty; t < SEQT; t += 8) {
        long o = rowbase + (long)t * DMODEL;
        sre += Dre[o]; sim += Dim[o];
    }
    red[ty][d] = sre; red2[ty][d] = sim;
    __syncthreads();
    if (ty == 0) {
        float a = 0.f, c = 0.f;
        for (int i = 0; i < 8; i++) { a += red[i][d]; c += red2[i][d]; }
        mre[d] = a * (1.f / SEQT); mim[d] = c * (1.f / SEQT);
    }
    __syncthreads();
    const float mr = mre[d], mi = mim[d];
    const float mn = sqrtf(mr * mr + mi * mi);

    float* gcol = gate + (long)bh * SEQT * DHEAD + d;   // + t*DHEAD

    // cosine similarity, track max
    float lmax = -1e30f;
    for (int t = ty; t < SEQT; t += 8) {
        long o = rowbase + (long)t * DMODEL;
        float re = Dre[o], im = Dim[o];
        float dot = re * mr + im * mi;
        float nrm = sqrtf(re * re + im * im) * mn + 1e-8f;
        float c = dot / nrm;
        gcol[(long)t * DHEAD] = c;
        lmax = fmaxf(lmax, c);
    }
    red[ty][d] = lmax;
    __syncthreads();
    if (ty == 0) {
        float m = -1e30f;
        for (int i = 0; i < 8; i++) m = fmaxf(m, red[i][d]);
        stat[d] = m;
    }
    __syncthreads();
    const float cmax = stat[d];
    __syncthreads();

    // exp + sum
    float lsum = 0.f;
    for (int t = ty; t < SEQT; t += 8) {
        float e = __expf(gcol[(long)t * DHEAD] - cmax);
        gcol[(long)t * DHEAD] = e;
        lsum += e;
    }
    red[ty][d] = lsum;
    __syncthreads();
    if (ty == 0) {
        float s = 0.f;
        for (int i = 0; i < 8; i++) s += red[i][d];
        stat[d] = s;
    }
    __syncthreads();
    const float inv = 1.f / stat[d];

    // normalize, gate V
    for (int t = ty; t < SEQT; t += 8) {
        float g = gcol[(long)t * DHEAD] * inv;
        gcol[(long)t * DHEAD] = g;
        long o = rowbase + (long)t * DMODEL;
        outp[o] = g * V[o];
    }
}

// -----------------------------------------------------------------------------
extern "C" void kernel_launch(void* const* d_in, const int* in_sizes, int n_in,
                              void* d_out, int out_size)
{
    const float* x   = (const float*)d_in[0];
    const float* WQ  = (const float*)d_in[1];
    const float* WK  = (const float*)d_in[2];
    const float* Wre = (const float*)d_in[3];
    const float* Wim = (const float*)d_in[4];
    const float* WV  = (const float*)d_in[5];
    const float* WO  = (const float*)d_in[6];
    const float* lam = (const float*)d_in[7];
    float* out = (float*)d_out;

    float *pQ, *pK, *pV, *pDreA, *pDimA, *pDreB, *pDimB, *pA, *pP, *pGateScr;
    cudaGetSymbolAddress((void**)&pQ, g_Q);
    cudaGetSymbolAddress((void**)&pK, g_K);
    cudaGetSymbolAddress((void**)&pV, g_V);
    cudaGetSymbolAddress((void**)&pDreA, g_DreA);
    cudaGetSymbolAddress((void**)&pDimA, g_DimA);
    cudaGetSymbolAddress((void**)&pDreB, g_DreB);
    cudaGetSymbolAddress((void**)&pDimB, g_DimB);
    cudaGetSymbolAddress((void**)&pA, g_A);
    cudaGetSymbolAddress((void**)&pP, g_P);
    cudaGetSymbolAddress((void**)&pGateScr, g_gate_scratch);

    const long OUT_ELEMS  = (long)BT * DMODEL;                 // 4,194,304
    const long GATE_ELEMS = (long)NBH * SEQT * DHEAD;          // 4,194,304
    float* gate = (out_size >= (int)(OUT_ELEMS + GATE_ELEMS)) ? (out + OUT_ELEMS)
                                                              : pGateScr;

    dim3 th(16, 16);
    dim3 gProj(DMODEL / 64, BT / 64, 1);       // 16 x 64

    // 5 projections (row-major (B*T, DM) outputs)
    gemm_k<false><<<gProj, th>>>(x, 0, 0, DMODEL, WQ, 0, 0, DMODEL,
                                 nullptr, 0, 0, 0, pQ, 0, 0, DMODEL,
                                 DMODEL, 1.f, 0.f, nullptr);
    gemm_k<false><<<gProj, th>>>(x, 0, 0, DMODEL, WK, 0, 0, DMODEL,
                                 nullptr, 0, 0, 0, pK, 0, 0, DMODEL,
                                 DMODEL, 1.f, 0.f, nullptr);
    gemm_k<false><<<gProj, th>>>(x, 0, 0, DMODEL, Wre, 0, 0, DMODEL,
                                 nullptr, 0, 0, 0, pDreA, 0, 0, DMODEL,
                                 DMODEL, 1.f, 0.f, nullptr);
    gemm_k<false><<<gProj, th>>>(x, 0, 0, DMODEL, Wim, 0, 0, DMODEL,
                                 nullptr, 0, 0, 0, pDimA, 0, 0, DMODEL,
                                 DMODEL, 1.f, 0.f, nullptr);
    gemm_k<false><<<gProj, th>>>(x, 0, 0, DMODEL, WV, 0, 0, DMODEL,
                                 nullptr, 0, 0, 0, pV, 0, 0, DMODEL,
                                 DMODEL, 1.f, 0.f, nullptr);

    // scores = Q @ K^T / 8 per (b,h). Q/K row-major, head offset h*64, batch b*T*DM
    const long sQb = (long)SEQT * DMODEL;   // per-b stride (outer)
    const long sQh = DHEAD;                 // per-h stride (inner)
    const long sAb = 16L * SEQT * SEQT;     // A per-b (16 heads)
    const long sAh = (long)SEQT * SEQT;     // A per-h
    dim3 gScore(SEQT / 64, SEQT / 64, NBH);
    gemm_k<true><<<gScore, th>>>(pQ, sQb, sQh, DMODEL, pK, sQb, sQh, DMODEL,
                                 nullptr, 0, 0, 0, pA, sAb, sAh, SEQT,
                                 DHEAD, 0.125f, 0.f, nullptr);

    // softmax over rows
    softmax_rows_k<<<NBH * SEQT, 256>>>(pA);

    // 3 propagation steps, re/im independently:  Dnew = lam*A@D + (1-lam)*D
    dim3 gProp(1, SEQT / 64, NBH);
    float* reSrc = pDreA; float* imSrc = pDimA;
    float* reDst = pDreB; float* imDst = pDimB;
    for (int s = 0; s < NSTEPS; s++) {
        gemm_k<false><<<gProp, th>>>(pA, sAb, sAh, SEQT,
                                     reSrc, sQb, sQh, DMODEL,
                                     reSrc, sQb, sQh, DMODEL,
                                     reDst, sQb, sQh, DMODEL,
                                     SEQT, 0.f, 0.f, lam);
        gemm_k<false><<<gProp, th>>>(pA, sAb, sAh, SEQT,
                                     imSrc, sQb, sQh, DMODEL,
                                     imSrc, sQb, sQh, DMODEL,
                                     imDst, sQb, sQh, DMODEL,
                                     SEQT, 0.f, 0.f, lam);
        float* t;
        t = reSrc; reSrc = reDst; reDst = t;
        t = imSrc; imSrc = imDst; imDst = t;
    }
    // after 3 steps result is in reSrc/imSrc

    // readout + gating
    readout_k<<<NBH, dim3(64, 8)>>>(reSrc, imSrc, pV, gate, pP);

    // out = P @ W_O
    gemm_k<false><<<gProj, th>>>(pP, 0, 0, DMODEL, WO, 0, 0, DMODEL,
                                 nullptr, 0, 0, 0, out, 0, 0, DMODEL,
                                 DMODEL, 1.f, 0.f, nullptr);
}

// round 4
// speedup vs baseline: 3.0245x; 3.0245x over previous
#include <cuda_runtime.h>
#include <cuda_bf16.h>
#include <math.h>
#include <stdint.h>

// Problem constants
#define BATCH 4
#define SEQT  1024
#define DMODEL 1024
#define NHEAD 16
#define DHEAD 64
#define NBH   (BATCH*NHEAD)      // 64
#define BT    (BATCH*SEQT)       // 4096
#define NSTEPS 3

#define HEADEL (NBH*SEQT*DHEAD)          // 4,194,304  (per-head QK / gate / DT element count)
#define AEL    ((size_t)NBH*SEQT*SEQT)   // 67,108,864 (adjacency)

// ---------------- scratch (device globals; no allocation allowed) ------------
__device__ float g_proj[(size_t)BT*5120];          // packed [Q|K|Dre|Dim|V] fp32
__device__ float g_S[AEL];                         // scores fp32
__device__ float g_DT[4L*HEADEL];                  // Dt fp32: [reim*2+pp][bh][d][t]
__device__ float g_gate_scratch[HEADEL];

__device__ __nv_bfloat16 g_xh[BT*DMODEL],  g_xl[BT*DMODEL];
__device__ __nv_bfloat16 g_W5h[5*DMODEL*DMODEL], g_W5l[5*DMODEL*DMODEL];
__device__ __nv_bfloat16 g_WOh[DMODEL*DMODEL],   g_WOl[DMODEL*DMODEL];
__device__ __nv_bfloat16 g_Qh[HEADEL], g_Ql[HEADEL], g_Kh[HEADEL], g_Kl[HEADEL];
__device__ __nv_bfloat16 g_Ah[AEL], g_Al[AEL];
__device__ __nv_bfloat16 g_DTh[4L*HEADEL], g_DTl[4L*HEADEL];
__device__ __nv_bfloat16 g_Ph[BT*DMODEL], g_Pl[BT*DMODEL];

// ---------------- PTX helpers ------------------------------------------------
__device__ __forceinline__ uint32_t smem_u32(const void* p) {
    return (uint32_t)__cvta_generic_to_shared(p);
}
__device__ __forceinline__ void cp16(uint32_t dst, const void* src) {
    asm volatile("cp.async.cg.shared.global [%0], [%1], 16;\n" :: "r"(dst), "l"(src));
}
__device__ __forceinline__ void cp_commit() { asm volatile("cp.async.commit_group;\n"); }
template<int N> __device__ __forceinline__ void cp_wait() {
    asm volatile("cp.async.wait_group %0;\n" :: "n"(N));
}
__device__ __forceinline__ void ldsm4(uint32_t& r0, uint32_t& r1, uint32_t& r2, uint32_t& r3, uint32_t addr) {
    asm volatile("ldmatrix.sync.aligned.m8n8.x4.shared.b16 {%0,%1,%2,%3}, [%4];\n"
                 : "=r"(r0), "=r"(r1), "=r"(r2), "=r"(r3) : "r"(addr));
}
__device__ __forceinline__ void mma16816(float* c, const uint32_t* a, const uint32_t* b) {
    asm volatile("mma.sync.aligned.m16n8k16.row.col.f32.bf16.bf16.f32 "
                 "{%0,%1,%2,%3}, {%4,%5,%6,%7}, {%8,%9}, {%0,%1,%2,%3};\n"
                 : "+f"(c[0]), "+f"(c[1]), "+f"(c[2]), "+f"(c[3])
                 : "r"(a[0]), "r"(a[1]), "r"(a[2]), "r"(a[3]), "r"(b[0]), "r"(b[1]));
}
__device__ __forceinline__ __nv_bfloat16 bf_hi(float v) { return __float2bfloat16(v); }
__device__ __forceinline__ __nv_bfloat16 bf_lo(float v, __nv_bfloat16 h) {
    return __float2bfloat16(v - __bfloat162float(h));
}

// ---------------- split-bf16 tensor-core GEMM --------------------------------
// C[m][n] = alpha * sum_k (A[m][k] * B[n][k])   (A row-major, B stored [n][k])
// 3-product split: Ah*Bh + Ah*Bl + Al*Bh.
// EPI==1 (propagation): v = lam*acc + (1-lam)*Cin; writes fp32 C and bf16 hi/lo.
// K % 32 == 0, M % BM == 0, N % BN == 0. BK = 32. 256 threads.
// smem layout: 16B chunks, phys_chunk = kchunk ^ ((row>>1)&3)  (conflict-free ldmatrix)
template<int BM, int BN, int WM, int WN, int EPI>
__global__ __launch_bounds__(256)
void mma_gemm(const __nv_bfloat16* __restrict__ Ahi, const __nv_bfloat16* __restrict__ Alo,
              long sA, int lda,
              const __nv_bfloat16* __restrict__ Bhi, const __nv_bfloat16* __restrict__ Blo,
              long sB, int ldb,
              float* __restrict__ C, long sC, int ldc,
              const float* __restrict__ Cin, long sI,
              __nv_bfloat16* __restrict__ Chi, __nv_bfloat16* __restrict__ Clo,
              int K, float alpha, const float* __restrict__ lam_ptr)
{
    constexpr int ACH = BM * 4;   // 16B chunks per A tile (BK=32 -> 4 chunks/row)
    constexpr int BCH = BN * 4;
    constexpr int MI = WM / 16;
    constexpr int NI = WN / 8;
    constexpr int WROWS = BM / WM;

    extern __shared__ uint4 sm[];
    uint4* sAh_ = sm;                     // [2][ACH]
    uint4* sAl_ = sAh_ + 2 * ACH;
    uint4* sBh_ = sAl_ + 2 * ACH;
    uint4* sBl_ = sBh_ + 2 * BCH;

    const int z = blockIdx.z;
    const __nv_bfloat16* pAh = Ahi + (long)z * sA;
    const __nv_bfloat16* pAl = Alo + (long)z * sA;
    const __nv_bfloat16* pBh = Bhi + (long)z * sB;
    const __nv_bfloat16* pBl = Blo + (long)z * sB;

    const int row0 = blockIdx.y * BM;
    const int col0 = blockIdx.x * BN;
    const int tid  = threadIdx.x;
    const int warp = tid >> 5, lane = tid & 31;
    const int wm = (warp % WROWS) * WM;
    const int wn = (warp / WROWS) * WN;

    float acc[MI][NI][4];
#pragma unroll
    for (int i = 0; i < MI; i++)
#pragma unroll
        for (int j = 0; j < NI; j++)
#pragma unroll
            for (int q = 0; q < 4; q++) acc[i][j][q] = 0.f;

    auto load_tile = [&](int st, int kt) {
#pragma unroll
        for (int i = tid; i < ACH; i += 256) {
            int r = i >> 2, c = i & 3;
            int phys = c ^ ((r >> 1) & 3);
            long src = (long)(row0 + r) * lda + kt * 32 + c * 8;
            cp16(smem_u32(&sAh_[st * ACH + r * 4 + phys]), pAh + src);
            cp16(smem_u32(&sAl_[st * ACH + r * 4 + phys]), pAl + src);
        }
#pragma unroll
        for (int i = tid; i < BCH; i += 256) {
            int r = i >> 2, c = i & 3;
            int phys = c ^ ((r >> 1) & 3);
            long src = (long)(col0 + r) * ldb + kt * 32 + c * 8;
            cp16(smem_u32(&sBh_[st * BCH + r * 4 + phys]), pBh + src);
            cp16(smem_u32(&sBl_[st * BCH + r * 4 + phys]), pBl + src);
        }
        cp_commit();
    };

    const int KT = K / 32;
    load_tile(0, 0);
    for (int kt = 0; kt < KT; kt++) {
        const int st = kt & 1;
        if (kt + 1 < KT) { load_tile(st ^ 1, kt + 1); cp_wait<1>(); }
        else             { cp_wait<0>(); }
        __syncthreads();

        const uint4* tAh = sAh_ + st * ACH;
        const uint4* tAl = sAl_ + st * ACH;
        const uint4* tBh = sBh_ + st * BCH;
        const uint4* tBl = sBl_ + st * BCH;
        const int tr = lane & 7;

#pragma unroll
        for (int ks8 = 0; ks8 < 2; ks8++) {   // two k16 steps per 32-tile
            uint32_t ah[MI][4], al[MI][4];
            const int akc = ks8 * 2 + (lane >> 4);
#pragma unroll
            for (int mi = 0; mi < MI; mi++) {
                int r = wm + mi * 16 + tr + ((lane >> 3) & 1) * 8;
                int off = r * 4 + (akc ^ ((r >> 1) & 3));
                ldsm4(ah[mi][0], ah[mi][1], ah[mi][2], ah[mi][3], smem_u32(tAh + off));
                ldsm4(al[mi][0], al[mi][1], al[mi][2], al[mi][3], smem_u32(tAl + off));
            }
            uint32_t bh[NI][2], bl[NI][2];
            const int bkc = ks8 * 2 + ((lane >> 3) & 1);
#pragma unroll
            for (int p = 0; p < NI / 2; p++) {
                int r = wn + p * 16 + tr + (lane >> 4) * 8;
                int off = r * 4 + (bkc ^ ((r >> 1) & 3));
                ldsm4(bh[2*p][0], bh[2*p][1], bh[2*p+1][0], bh[2*p+1][1], smem_u32(tBh + off));
                ldsm4(bl[2*p][0], bl[2*p][1], bl[2*p+1][0], bl[2*p+1][1], smem_u32(tBl + off));
            }
#pragma unroll
            for (int mi = 0; mi < MI; mi++)
#pragma unroll
                for (int ni = 0; ni < NI; ni++) {
                    mma16816(acc[mi][ni], ah[mi], bh[ni]);
                    mma16816(acc[mi][ni], ah[mi], bl[ni]);
                    mma16816(acc[mi][ni], al[mi], bh[ni]);
                }
        }
        __syncthreads();
    }

    // ------- epilogue -------
    float al_ = alpha, be_ = 0.f;
    if (EPI == 1) {
        float lm = 1.f / (1.f + __expf(-lam_ptr[0]));
        al_ = lm; be_ = 1.f - lm;
    }
    const long zC = (long)z * sC;
    const long zI = (long)z * sI;
    const int g = lane >> 2, tig = lane & 3;
#pragma unroll
    for (int mi = 0; mi < MI; mi++) {
#pragma unroll
        for (int ni = 0; ni < NI; ni++) {
            int r = row0 + wm + mi * 16 + g;
            int cc = col0 + wn + ni * 8 + tig * 2;
#pragma unroll
            for (int half = 0; half < 2; half++) {
                int rr = r + half * 8;
                float v0 = al_ * acc[mi][ni][half * 2 + 0];
                float v1 = al_ * acc[mi][ni][half * 2 + 1];
                long o = zC + (long)rr * ldc + cc;
                if (EPI == 1) {
                    long oi = zI + (long)rr * ldc + cc;
                    v0 += be_ * Cin[oi];
                    v1 += be_ * Cin[oi + 1];
                }
                float2 f2; f2.x = v0; f2.y = v1;
                *(float2*)&C[o] = f2;
                if (EPI == 1) {
                    __nv_bfloat162 hv, lv;
                    hv.x = bf_hi(v0); hv.y = bf_hi(v1);
                    lv.x = bf_lo(v0, hv.x); lv.y = bf_lo(v1, hv.y);
                    *(__nv_bfloat162*)&Chi[o] = hv;
                    *(__nv_bfloat162*)&Clo[o] = lv;
                }
            }
        }
    }
}

// ---------------- conversions ------------------------------------------------
__global__ void split_ew_k(const float* __restrict__ src,
                           __nv_bfloat16* __restrict__ hi, __nv_bfloat16* __restrict__ lo, int n)
{
    int i = blockIdx.x * 256 + threadIdx.x;
    if (i < n) {
        float v = src[i];
        __nv_bfloat16 h = bf_hi(v);
        hi[i] = h; lo[i] = bf_lo(v, h);
    }
}

// W [1024][1024] (k rows, n cols) -> out [n][k] split
__global__ void splitT_w_k(const float* __restrict__ W,
                           __nv_bfloat16* __restrict__ hi, __nv_bfloat16* __restrict__ lo)
{
    __shared__ float t[32][33];
    int k0 = blockIdx.y * 32, n0 = blockIdx.x * 32;
    for (int i = threadIdx.y; i < 32; i += 8)
        t[i][threadIdx.x] = W[(k0 + i) * DMODEL + n0 + threadIdx.x];
    __syncthreads();
    for (int i = threadIdx.y; i < 32; i += 8) {
        float v = t[threadIdx.x][i];             // W[k0+tx][n0+i]
        __nv_bfloat16 h = bf_hi(v);
        long o = (long)(n0 + i) * DMODEL + k0 + threadIdx.x;
        hi[o] = h; lo[o] = bf_lo(v, h);
    }
}

// proj column slice -> per-head [bh][t][d] split (no transpose)
__global__ void split_heads_k(const float* __restrict__ proj, int coloff,
                              __nv_bfloat16* __restrict__ hi, __nv_bfloat16* __restrict__ lo)
{
    int i = blockIdx.x * 256 + threadIdx.x;     // over NBH*SEQT*DHEAD
    int d = i & 63, t = (i >> 6) & 1023, bh = i >> 16;
    int b = bh >> 4, h = bh & 15;
    float v = proj[((long)(b * SEQT + t)) * 5120 + coloff + h * DHEAD + d];
    __nv_bfloat16 hh = bf_hi(v);
    hi[i] = hh; lo[i] = bf_lo(v, hh);
}

// proj D slice -> transposed [bh][d][t], fp32 + split
__global__ void split_D_init_k(const float* __restrict__ proj, int coloff,
                               float* __restrict__ f,
                               __nv_bfloat16* __restrict__ hi, __nv_bfloat16* __restrict__ lo)
{
    __shared__ float tb[32][33];
    int bh = blockIdx.z, b = bh >> 4, h = bh & 15;
    int t0 = blockIdx.x * 32, d0 = blockIdx.y * 32;
    for (int i = threadIdx.y; i < 32; i += 8)
        tb[i][threadIdx.x] = proj[((long)(b * SEQT + t0 + i)) * 5120 + coloff + h * DHEAD + d0 + threadIdx.x];
    __syncthreads();
    long base = (long)bh * (DHEAD * SEQT);
    for (int i = threadIdx.y; i < 32; i += 8) {
        float v = tb[threadIdx.x][i];            // (t=t0+tx, d=d0+i)
        long o = base + (long)(d0 + i) * SEQT + t0 + threadIdx.x;
        __nv_bfloat16 hh = bf_hi(v);
        f[o] = v; hi[o] = hh; lo[o] = bf_lo(v, hh);
    }
}

// ---------------- softmax over rows of 1024, writes bf16 hi/lo ---------------
__global__ void softmax_split_k(const float* __restrict__ S,
                                __nv_bfloat16* __restrict__ Ah, __nv_bfloat16* __restrict__ Al)
{
    const float* p = S + (long)blockIdx.x * SEQT;
    long ob = (long)blockIdx.x * SEQT;
    const int tid = threadIdx.x;
    __shared__ float sh[8];

    float m = -1e30f;
    for (int i = tid; i < SEQT; i += 256) m = fmaxf(m, p[i]);
#pragma unroll
    for (int o = 16; o; o >>= 1) m = fmaxf(m, __shfl_xor_sync(0xffffffffu, m, o));
    if ((tid & 31) == 0) sh[tid >> 5] = m;
    __syncthreads();
    if (tid == 0) {
        float mm = sh[0];
        for (int i = 1; i < 8; i++) mm = fmaxf(mm, sh[i]);
        sh[0] = mm;
    }
    __syncthreads();
    m = sh[0];
    __syncthreads();

    float s = 0.f;
    for (int i = tid; i < SEQT; i += 256) s += __expf(p[i] - m);
#pragma unroll
    for (int o = 16; o; o >>= 1) s += __shfl_xor_sync(0xffffffffu, s, o);
    if ((tid & 31) == 0) sh[tid >> 5] = s;
    __syncthreads();
    if (tid == 0) {
        float ss = 0.f;
        for (int i = 0; i < 8; i++) ss += sh[i];
        sh[0] = ss;
    }
    __syncthreads();
    const float inv = 1.f / sh[0];

    for (int i = tid; i < SEQT; i += 256) {
        float v = __expf(p[i] - m) * inv;
        __nv_bfloat16 h = bf_hi(v);
        Ah[ob + i] = h; Al[ob + i] = bf_lo(v, h);
    }
}

// ---------------- readout on transposed D: one warp per (bh,d) row -----------
__global__ void readout2_k(const float* __restrict__ Dre, const float* __restrict__ Dim,
                           const float* __restrict__ proj,
                           float* __restrict__ gate,
                           __nv_bfloat16* __restrict__ Ph, __nv_bfloat16* __restrict__ Pl)
{
    int warp = threadIdx.x >> 5, lane = threadIdx.x & 31;
    int gid = blockIdx.x * 8 + warp;            // 0..4095
    int bh = gid >> 6, d = gid & 63;
    int b = bh >> 4, h = bh & 15;
    const float* rre = Dre + (long)bh * (DHEAD * SEQT) + d * SEQT;
    const float* rim = Dim + (long)bh * (DHEAD * SEQT) + d * SEQT;

    float re[32], im[32];
    float sre = 0.f, sim = 0.f;
#pragma unroll
    for (int j = 0; j < 32; j++) {
        re[j] = rre[lane + j * 32]; im[j] = rim[lane + j * 32];
        sre += re[j]; sim += im[j];
    }
#pragma unroll
    for (int o = 16; o; o >>= 1) {
        sre += __shfl_xor_sync(0xffffffffu, sre, o);
        sim += __shfl_xor_sync(0xffffffffu, sim, o);
    }
    float mr = sre * (1.f / SEQT), mi = sim * (1.f / SEQT);
    float mn = sqrtf(mr * mr + mi * mi);

    float cs[32]; float mx = -1e30f;
#pragma unroll
    for (int j = 0; j < 32; j++) {
        float dot = re[j] * mr + im[j] * mi;
        float nrm = sqrtf(re[j] * re[j] + im[j] * im[j]) * mn + 1e-8f;
        cs[j] = dot / nrm;
        mx = fmaxf(mx, cs[j]);
    }
#pragma unroll
    for (int o = 16; o; o >>= 1) mx = fmaxf(mx, __shfl_xor_sync(0xffffffffu, mx, o));
    float s = 0.f;
#pragma unroll
    for (int j = 0; j < 32; j++) { cs[j] = __expf(cs[j] - mx); s += cs[j]; }
#pragma unroll
    for (int o = 16; o; o >>= 1) s += __shfl_xor_sync(0xffffffffu, s, o);
    float inv = 1.f / s;

#pragma unroll
    for (int j = 0; j < 32; j++) {
        int t = lane + j * 32;
        float g = cs[j] * inv;
        gate[(long)bh * (SEQT * DHEAD) + t * DHEAD + d] = g;
        float v = proj[((long)(b * SEQT + t)) * 5120 + 4096 + h * DHEAD + d];
        float pv = g * v;
        __nv_bfloat16 hh = bf_hi(pv);
        long po = ((long)(b * SEQT + t)) * DMODEL + h * DHEAD + d;
        Ph[po] = hh; Pl[po] = bf_lo(pv, hh);
    }
}

// -----------------------------------------------------------------------------
extern "C" void kernel_launch(void* const* d_in, const int* in_sizes, int n_in,
                              void* d_out, int out_size)
{
    const float* x   = (const float*)d_in[0];
    const float* WQ  = (const float*)d_in[1];
    const float* WK  = (const float*)d_in[2];
    const float* Wre = (const float*)d_in[3];
    const float* Wim = (const float*)d_in[4];
    const float* WV  = (const float*)d_in[5];
    const float* WO  = (const float*)d_in[6];
    const float* lam = (const float*)d_in[7];
    float* out = (float*)d_out;

    float *pproj, *pS, *pDT, *pGateScr;
    __nv_bfloat16 *pxh, *pxl, *pW5h, *pW5l, *pWOh, *pWOl;
    __nv_bfloat16 *pQh, *pQl, *pKh, *pKl, *pAh, *pAl, *pDTh, *pDTl, *pPh, *pPl;
    cudaGetSymbolAddress((void**)&pproj, g_proj);
    cudaGetSymbolAddress((void**)&pS, g_S);
    cudaGetSymbolAddress((void**)&pDT, g_DT);
    cudaGetSymbolAddress((void**)&pGateScr, g_gate_scratch);
    cudaGetSymbolAddress((void**)&pxh, g_xh);
    cudaGetSymbolAddress((void**)&pxl, g_xl);
    cudaGetSymbolAddress((void**)&pW5h, g_W5h);
    cudaGetSymbolAddress((void**)&pW5l, g_W5l);
    cudaGetSymbolAddress((void**)&pWOh, g_WOh);
    cudaGetSymbolAddress((void**)&pWOl, g_WOl);
    cudaGetSymbolAddress((void**)&pQh, g_Qh);
    cudaGetSymbolAddress((void**)&pQl, g_Ql);
    cudaGetSymbolAddress((void**)&pKh, g_Kh);
    cudaGetSymbolAddress((void**)&pKl, g_Kl);
    cudaGetSymbolAddress((void**)&pAh, g_Ah);
    cudaGetSymbolAddress((void**)&pAl, g_Al);
    cudaGetSymbolAddress((void**)&pDTh, g_DTh);
    cudaGetSymbolAddress((void**)&pDTl, g_DTl);
    cudaGetSymbolAddress((void**)&pPh, g_Ph);
    cudaGetSymbolAddress((void**)&pPl, g_Pl);

    const long OUT_ELEMS  = (long)BT * DMODEL;
    const long GATE_ELEMS = (long)HEADEL;
    float* gate = (out_size >= (int)(OUT_ELEMS + GATE_ELEMS)) ? (out + OUT_ELEMS) : pGateScr;

    const int SMEM_A = 65536;   // cfg 128x128
    const int SMEM_B = 49152;   // cfg 64x128
    cudaFuncSetAttribute(mma_gemm<128,128,64,32,0>, cudaFuncAttributeMaxDynamicSharedMemorySize, SMEM_A);
    cudaFuncSetAttribute(mma_gemm<64,128,32,32,1>,  cudaFuncAttributeMaxDynamicSharedMemorySize, SMEM_B);

    // ---- input splits ----
    split_ew_k<<<(BT * DMODEL + 255) / 256, 256>>>(x, pxh, pxl, BT * DMODEL);
    dim3 tb(32, 8), tg(32, 32);
    const float* Ws[5] = {WQ, WK, Wre, Wim, WV};
    for (int w = 0; w < 5; w++)
        splitT_w_k<<<tg, tb>>>(Ws[w], pW5h + (long)w * DMODEL * DMODEL, pW5l + (long)w * DMODEL * DMODEL);
    splitT_w_k<<<tg, tb>>>(WO, pWOh, pWOl);

    // ---- fused 5-way projection: [4096,5120] = x @ [WQ|WK|Wre|Wim|WV] ----
    mma_gemm<128,128,64,32,0><<<dim3(5120/128, BT/128, 1), 256, SMEM_A>>>(
        pxh, pxl, 0, DMODEL, pW5h, pW5l, 0, DMODEL,
        pproj, 0, 5120, nullptr, 0, nullptr, nullptr, DMODEL, 1.f, nullptr);

    // ---- per-head splits of Q, K; transposed split of Dre, Dim ----
    split_heads_k<<<HEADEL / 256, 256>>>(pproj, 0,    pQh, pQl);
    split_heads_k<<<HEADEL / 256, 256>>>(pproj, 1024, pKh, pKl);
    split_D_init_k<<<dim3(32, 2, NBH), tb>>>(pproj, 2048, pDT + 0L * HEADEL, pDTh + 0L * HEADEL, pDTl + 0L * HEADEL);
    split_D_init_k<<<dim3(32, 2, NBH), tb>>>(pproj, 3072, pDT + 2L * HEADEL, pDTh + 2L * HEADEL, pDTl + 2L * HEADEL);

    // ---- scores: S[bh][t][s] = Q @ K^T / 8 ----
    mma_gemm<128,128,64,32,0><<<dim3(8, 8, NBH), 256, SMEM_A>>>(
        pQh, pQl, (long)SEQT * DHEAD, DHEAD,
        pKh, pKl, (long)SEQT * DHEAD, DHEAD,
        pS, (long)SEQT * SEQT, SEQT, nullptr, 0, nullptr, nullptr, DHEAD, 0.125f, nullptr);

    // ---- softmax rows -> A bf16 hi/lo ----
    softmax_split_k<<<NBH * SEQT, 256>>>(pS, pAh, pAl);

    // ---- propagation: Dt' = lam * (Dt @ A^T) + (1-lam) * Dt, 3 steps ----
    for (int s = 0; s < NSTEPS; s++) {
        int in = s & 1, op = 1 - in;
        for (int ri = 0; ri < 2; ri++) {
            long iin = (long)(ri * 2 + in) * HEADEL;
            long iou = (long)(ri * 2 + op) * HEADEL;
            mma_gemm<64,128,32,32,1><<<dim3(8, 1, NBH), 256, SMEM_B>>>(
                pDTh + iin, pDTl + iin, (long)DHEAD * SEQT, SEQT,
                pAh, pAl, (long)SEQT * SEQT, SEQT,
                pDT + iou, (long)DHEAD * SEQT, SEQT,
                pDT + iin, (long)DHEAD * SEQT,
                pDTh + iou, pDTl + iou,
                SEQT, 0.f, lam);
        }
    }
    // after 3 steps final is pp index 1

    // ---- readout + gating (writes gate + P hi/lo) ----
    readout2_k<<<NBH * DHEAD / 8, 256>>>(pDT + 1L * HEADEL, pDT + 3L * HEADEL,
                                         pproj, gate, pPh, pPl);

    // ---- out = P @ W_O ----
    mma_gemm<128,128,64,32,0><<<dim3(DMODEL/128, BT/128, 1), 256, SMEM_A>>>(
        pPh, pPl, 0, DMODEL, pWOh, pWOl, 0, DMODEL,
        out, 0, DMODEL, nullptr, 0, nullptr, nullptr, DMODEL, 1.f, nullptr);
}

// round 5
// speedup vs baseline: 3.4360x; 1.1361x over previous
#include <cuda_runtime.h>
#include <cuda_bf16.h>
#include <math.h>
#include <stdint.h>

// Problem constants
#define BATCH 4
#define SEQT  1024
#define DMODEL 1024
#define NHEAD 16
#define DHEAD 64
#define NBH   (BATCH*NHEAD)      // 64
#define BT    (BATCH*SEQT)       // 4096
#define NSTEPS 3

#define HEADEL (NBH*SEQT*DHEAD)          // 4,194,304
#define FEL    (2L*HEADEL)               // fused re|im D buffer: [bh][128][1024]
#define AEL    ((size_t)NBH*SEQT*SEQT)   // 67,108,864

// ---------------- scratch (device globals; no allocation allowed) ------------
__device__ float g_proj[(size_t)BT*5120];          // packed [Q|K|Dre|Dim|V] fp32
__device__ float g_S[AEL];                         // scores fp32
__device__ float g_DT[2L*FEL];                     // D fused: [pp][bh][reim*64+d][t]
__device__ float g_gate_scratch[HEADEL];

__device__ __nv_bfloat16 g_xh[BT*DMODEL],  g_xl[BT*DMODEL];
__device__ __nv_bfloat16 g_W5h[5*DMODEL*DMODEL], g_W5l[5*DMODEL*DMODEL];
__device__ __nv_bfloat16 g_WOh[DMODEL*DMODEL],   g_WOl[DMODEL*DMODEL];
__device__ __nv_bfloat16 g_Qh[HEADEL], g_Ql[HEADEL], g_Kh[HEADEL], g_Kl[HEADEL];
__device__ __nv_bfloat16 g_Ah[AEL], g_Al[AEL];
__device__ __nv_bfloat16 g_DTh[2L*FEL], g_DTl[2L*FEL];
__device__ __nv_bfloat16 g_Ph[BT*DMODEL], g_Pl[BT*DMODEL];

// ---------------- PTX helpers ------------------------------------------------
__device__ __forceinline__ uint32_t smem_u32(const void* p) {
    return (uint32_t)__cvta_generic_to_shared(p);
}
__device__ __forceinline__ void cp16(uint32_t dst, const void* src) {
    asm volatile("cp.async.cg.shared.global [%0], [%1], 16;\n" :: "r"(dst), "l"(src));
}
__device__ __forceinline__ void cp_commit() { asm volatile("cp.async.commit_group;\n"); }
template<int N> __device__ __forceinline__ void cp_wait() {
    asm volatile("cp.async.wait_group %0;\n" :: "n"(N));
}
__device__ __forceinline__ void ldsm4(uint32_t& r0, uint32_t& r1, uint32_t& r2, uint32_t& r3, uint32_t addr) {
    asm volatile("ldmatrix.sync.aligned.m8n8.x4.shared.b16 {%0,%1,%2,%3}, [%4];\n"
                 : "=r"(r0), "=r"(r1), "=r"(r2), "=r"(r3) : "r"(addr));
}
__device__ __forceinline__ void mma16816(float* c, const uint32_t* a, const uint32_t* b) {
    asm volatile("mma.sync.aligned.m16n8k16.row.col.f32.bf16.bf16.f32 "
                 "{%0,%1,%2,%3}, {%4,%5,%6,%7}, {%8,%9}, {%0,%1,%2,%3};\n"
                 : "+f"(c[0]), "+f"(c[1]), "+f"(c[2]), "+f"(c[3])
                 : "r"(a[0]), "r"(a[1]), "r"(a[2]), "r"(a[3]), "r"(b[0]), "r"(b[1]));
}
__device__ __forceinline__ __nv_bfloat16 bf_hi(float v) { return __float2bfloat16(v); }
__device__ __forceinline__ __nv_bfloat16 bf_lo(float v, __nv_bfloat16 h) {
    return __float2bfloat16(v - __bfloat162float(h));
}

// ---------------- split-bf16 tensor-core GEMM --------------------------------
// C[m][n] = alpha * sum_k (A[m][k] * B[n][k])   (A row-major, B stored [n][k])
// 3-product split: Ah*Bh + Ah*Bl + Al*Bh.
// EPI==1: v = lam*acc + (1-lam)*Cin; writes fp32 C AND bf16 hi/lo for next step.
// K % 32 == 0. BK = 32. 256 threads. STAGES-deep cp.async ring.
// smem swizzle: phys_chunk = kchunk ^ ((row>>1)&3)  (conflict-free ldmatrix)
template<int BM, int BN, int WM, int WN, int EPI, int STAGES>
__global__ __launch_bounds__(256)
void mma_gemm(const __nv_bfloat16* __restrict__ Ahi, const __nv_bfloat16* __restrict__ Alo,
              long sA, int lda,
              const __nv_bfloat16* __restrict__ Bhi, const __nv_bfloat16* __restrict__ Blo,
              long sB, int ldb,
              float* __restrict__ C, long sC, int ldc,
              const float* __restrict__ Cin, long sI,
              __nv_bfloat16* __restrict__ Chi, __nv_bfloat16* __restrict__ Clo,
              int K, float alpha, const float* __restrict__ lam_ptr)
{
    constexpr int ACH = BM * 4;   // 16B chunks per A tile (BK=32 -> 4 chunks/row)
    constexpr int BCH = BN * 4;
    constexpr int MI = WM / 16;
    constexpr int NI = WN / 8;
    constexpr int WROWS = BM / WM;

    extern __shared__ uint4 sm[];
    uint4* sAh_ = sm;                          // [STAGES][ACH]
    uint4* sAl_ = sAh_ + STAGES * ACH;
    uint4* sBh_ = sAl_ + STAGES * ACH;
    uint4* sBl_ = sBh_ + STAGES * BCH;

    const int z = blockIdx.z;
    const __nv_bfloat16* pAh = Ahi + (long)z * sA;
    const __nv_bfloat16* pAl = Alo + (long)z * sA;
    const __nv_bfloat16* pBh = Bhi + (long)z * sB;
    const __nv_bfloat16* pBl = Blo + (long)z * sB;

    const int row0 = blockIdx.y * BM;
    const int col0 = blockIdx.x * BN;
    const int tid  = threadIdx.x;
    const int warp = tid >> 5, lane = tid & 31;
    const int wm = (warp % WROWS) * WM;
    const int wn = (warp / WROWS) * WN;

    float acc[MI][NI][4];
#pragma unroll
    for (int i = 0; i < MI; i++)
#pragma unroll
        for (int j = 0; j < NI; j++)
#pragma unroll
            for (int q = 0; q < 4; q++) acc[i][j][q] = 0.f;

    auto load_tile = [&](int st, int kt) {
#pragma unroll
        for (int i = tid; i < ACH; i += 256) {
            int r = i >> 2, c = i & 3;
            int phys = c ^ ((r >> 1) & 3);
            long src = (long)(row0 + r) * lda + kt * 32 + c * 8;
            cp16(smem_u32(&sAh_[st * ACH + r * 4 + phys]), pAh + src);
            cp16(smem_u32(&sAl_[st * ACH + r * 4 + phys]), pAl + src);
        }
#pragma unroll
        for (int i = tid; i < BCH; i += 256) {
            int r = i >> 2, c = i & 3;
            int phys = c ^ ((r >> 1) & 3);
            long src = (long)(col0 + r) * ldb + kt * 32 + c * 8;
            cp16(smem_u32(&sBh_[st * BCH + r * 4 + phys]), pBh + src);
            cp16(smem_u32(&sBl_[st * BCH + r * 4 + phys]), pBl + src);
        }
        cp_commit();
    };

    const int KT = K / 32;
#pragma unroll
    for (int i = 0; i < STAGES - 1; i++) {
        if (i < KT) load_tile(i, i);
        else cp_commit();
    }

    for (int kt = 0; kt < KT; kt++) {
        cp_wait<STAGES - 2>();
        __syncthreads();                       // tile kt ready; prior stage fully consumed

        {   // issue next tile into the slot freed at kt-1
            int next = kt + STAGES - 1;
            if (next < KT) load_tile(next % STAGES, next);
            else cp_commit();                  // empty group keeps wait arithmetic valid
        }

        const int st = kt % STAGES;
        const uint4* tAh = sAh_ + st * ACH;
        const uint4* tAl = sAl_ + st * ACH;
        const uint4* tBh = sBh_ + st * BCH;
        const uint4* tBl = sBl_ + st * BCH;
        const int tr = lane & 7;

#pragma unroll
        for (int ks8 = 0; ks8 < 2; ks8++) {   // two k16 steps per 32-tile
            uint32_t ah[MI][4], al[MI][4];
            const int akc = ks8 * 2 + (lane >> 4);
#pragma unroll
            for (int mi = 0; mi < MI; mi++) {
                int r = wm + mi * 16 + tr + ((lane >> 3) & 1) * 8;
                int off = r * 4 + (akc ^ ((r >> 1) & 3));
                ldsm4(ah[mi][0], ah[mi][1], ah[mi][2], ah[mi][3], smem_u32(tAh + off));
                ldsm4(al[mi][0], al[mi][1], al[mi][2], al[mi][3], smem_u32(tAl + off));
            }
            uint32_t bh[NI][2], bl[NI][2];
            const int bkc = ks8 * 2 + ((lane >> 3) & 1);
#pragma unroll
            for (int p = 0; p < NI / 2; p++) {
                int r = wn + p * 16 + tr + (lane >> 4) * 8;
                int off = r * 4 + (bkc ^ ((r >> 1) & 3));
                ldsm4(bh[2*p][0], bh[2*p][1], bh[2*p+1][0], bh[2*p+1][1], smem_u32(tBh + off));
                ldsm4(bl[2*p][0], bl[2*p][1], bl[2*p+1][0], bl[2*p+1][1], smem_u32(tBl + off));
            }
#pragma unroll
            for (int mi = 0; mi < MI; mi++)
#pragma unroll
                for (int ni = 0; ni < NI; ni++) {
                    mma16816(acc[mi][ni], ah[mi], bh[ni]);
                    mma16816(acc[mi][ni], ah[mi], bl[ni]);
                    mma16816(acc[mi][ni], al[mi], bh[ni]);
                }
        }
    }

    // ------- epilogue -------
    float al_ = alpha, be_ = 0.f;
    if (EPI == 1) {
        float lm = 1.f / (1.f + __expf(-lam_ptr[0]));
        al_ = lm; be_ = 1.f - lm;
    }
    const long zC = (long)z * sC;
    const long zI = (long)z * sI;
    const int g = lane >> 2, tig = lane & 3;
#pragma unroll
    for (int mi = 0; mi < MI; mi++) {
#pragma unroll
        for (int ni = 0; ni < NI; ni++) {
            int r = row0 + wm + mi * 16 + g;
            int cc = col0 + wn + ni * 8 + tig * 2;
#pragma unroll
            for (int half = 0; half < 2; half++) {
                int rr = r + half * 8;
                float v0 = al_ * acc[mi][ni][half * 2 + 0];
                float v1 = al_ * acc[mi][ni][half * 2 + 1];
                long o = zC + (long)rr * ldc + cc;
                if (EPI == 1) {
                    long oi = zI + (long)rr * ldc + cc;
                    v0 += be_ * Cin[oi];
                    v1 += be_ * Cin[oi + 1];
                }
                float2 f2; f2.x = v0; f2.y = v1;
                *(float2*)&C[o] = f2;
                if (EPI == 1) {
                    __nv_bfloat162 hv, lv;
                    hv.x = bf_hi(v0); hv.y = bf_hi(v1);
                    lv.x = bf_lo(v0, hv.x); lv.y = bf_lo(v1, hv.y);
                    *(__nv_bfloat162*)&Chi[o] = hv;
                    *(__nv_bfloat162*)&Clo[o] = lv;
                }
            }
        }
    }
}

// ---------------- conversions ------------------------------------------------
__global__ void split_ew_k(const float* __restrict__ src,
                           __nv_bfloat16* __restrict__ hi, __nv_bfloat16* __restrict__ lo, int n)
{
    int i = blockIdx.x * 256 + threadIdx.x;
    if (i < n) {
        float v = src[i];
        __nv_bfloat16 h = bf_hi(v);
        hi[i] = h; lo[i] = bf_lo(v, h);
    }
}

// W [1024][1024] (k rows, n cols) -> out [n][k] split
__global__ void splitT_w_k(const float* __restrict__ W,
                           __nv_bfloat16* __restrict__ hi, __nv_bfloat16* __restrict__ lo)
{
    __shared__ float t[32][33];
    int k0 = blockIdx.y * 32, n0 = blockIdx.x * 32;
    for (int i = threadIdx.y; i < 32; i += 8)
        t[i][threadIdx.x] = W[(k0 + i) * DMODEL + n0 + threadIdx.x];
    __syncthreads();
    for (int i = threadIdx.y; i < 32; i += 8) {
        float v = t[threadIdx.x][i];             // W[k0+tx][n0+i]
        __nv_bfloat16 h = bf_hi(v);
        long o = (long)(n0 + i) * DMODEL + k0 + threadIdx.x;
        hi[o] = h; lo[o] = bf_lo(v, h);
    }
}

// proj column slice -> per-head [bh][t][d] split (no transpose)
__global__ void split_heads_k(const float* __restrict__ proj, int coloff,
                              __nv_bfloat16* __restrict__ hi, __nv_bfloat16* __restrict__ lo)
{
    int i = blockIdx.x * 256 + threadIdx.x;     // over NBH*SEQT*DHEAD
    int d = i & 63, t = (i >> 6) & 1023, bh = i >> 16;
    int b = bh >> 4, h = bh & 15;
    float v = proj[((long)(b * SEQT + t)) * 5120 + coloff + h * DHEAD + d];
    __nv_bfloat16 hh = bf_hi(v);
    hi[i] = hh; lo[i] = bf_lo(v, hh);
}

// proj D slice -> fused transposed [bh][rowoff+d][t], fp32 + split
__global__ void split_D_init_k(const float* __restrict__ proj, int coloff, int rowoff,
                               float* __restrict__ f,
                               __nv_bfloat16* __restrict__ hi, __nv_bfloat16* __restrict__ lo)
{
    __shared__ float tb[32][33];
    int bh = blockIdx.z, b = bh >> 4, h = bh & 15;
    int t0 = blockIdx.x * 32, d0 = blockIdx.y * 32;
    for (int i = threadIdx.y; i < 32; i += 8)
        tb[i][threadIdx.x] = proj[((long)(b * SEQT + t0 + i)) * 5120 + coloff + h * DHEAD + d0 + threadIdx.x];
    __syncthreads();
    long base = (long)bh * (128 * SEQT);
    for (int i = threadIdx.y; i < 32; i += 8) {
        float v = tb[threadIdx.x][i];            // (t=t0+tx, d=d0+i)
        long o = base + (long)(rowoff + d0 + i) * SEQT + t0 + threadIdx.x;
        __nv_bfloat16 hh = bf_hi(v);
        f[o] = v; hi[o] = hh; lo[o] = bf_lo(v, hh);
    }
}

// ---------------- single-pass softmax over rows of 1024, writes bf16 hi/lo ---
__global__ void softmax_split_k(const float* __restrict__ S,
                                __nv_bfloat16* __restrict__ Ah, __nv_bfloat16* __restrict__ Al)
{
    const long rb = (long)blockIdx.x * SEQT;
    const int tid = threadIdx.x;
    __shared__ float sh[8];

    float4 v = *(const float4*)(S + rb + tid * 4);

    float m = fmaxf(fmaxf(v.x, v.y), fmaxf(v.z, v.w));
#pragma unroll
    for (int o = 16; o; o >>= 1) m = fmaxf(m, __shfl_xor_sync(0xffffffffu, m, o));
    if ((tid & 31) == 0) sh[tid >> 5] = m;
    __syncthreads();
    if (tid < 8) {
        float mm = sh[tid];
#pragma unroll
        for (int o = 4; o; o >>= 1) mm = fmaxf(mm, __shfl_xor_sync(0xffu, mm, o));
        sh[tid] = mm;
    }
    __syncthreads();
    m = sh[0];
    __syncthreads();

    float e0 = __expf(v.x - m), e1 = __expf(v.y - m);
    float e2 = __expf(v.z - m), e3 = __expf(v.w - m);
    float s = e0 + e1 + e2 + e3;
#pragma unroll
    for (int o = 16; o; o >>= 1) s += __shfl_xor_sync(0xffffffffu, s, o);
    if ((tid & 31) == 0) sh[tid >> 5] = s;
    __syncthreads();
    if (tid < 8) {
        float ss = sh[tid];
#pragma unroll
        for (int o = 4; o; o >>= 1) ss += __shfl_xor_sync(0xffu, ss, o);
        sh[tid] = ss;
    }
    __syncthreads();
    const float inv = 1.f / sh[0];

    e0 *= inv; e1 *= inv; e2 *= inv; e3 *= inv;
    __nv_bfloat162 h01, h23, l01, l23;
    h01.x = bf_hi(e0); h01.y = bf_hi(e1);
    h23.x = bf_hi(e2); h23.y = bf_hi(e3);
    l01.x = bf_lo(e0, h01.x); l01.y = bf_lo(e1, h01.y);
    l23.x = bf_lo(e2, h23.x); l23.y = bf_lo(e3, h23.y);
    *(__nv_bfloat162*)(Ah + rb + tid * 4)     = h01;
    *(__nv_bfloat162*)(Ah + rb + tid * 4 + 2) = h23;
    *(__nv_bfloat162*)(Al + rb + tid * 4)     = l01;
    *(__nv_bfloat162*)(Al + rb + tid * 4 + 2) = l23;
}

// ---------------- readout on fused transposed D: one warp per (bh,d) row -----
__global__ void readout2_k(const float* __restrict__ F,   // [bh][128][1024], re rows 0-63
                           const float* __restrict__ proj,
                           float* __restrict__ gate,
                           __nv_bfloat16* __restrict__ Ph, __nv_bfloat16* __restrict__ Pl)
{
    int warp = threadIdx.x >> 5, lane = threadIdx.x & 31;
    int gid = blockIdx.x * 8 + warp;            // 0..4095
    int bh = gid >> 6, d = gid & 63;
    int b = bh >> 4, h = bh & 15;
    const float* rre = F + (long)bh * (128 * SEQT) + d * SEQT;
    const float* rim = rre + 64 * SEQT;

    float re[32], im[32];
    float sre = 0.f, sim = 0.f;
#pragma unroll
    for (int j = 0; j < 32; j++) {
        re[j] = rre[lane + j * 32]; im[j] = rim[lane + j * 32];
        sre += re[j]; sim += im[j];
    }
#pragma unroll
    for (int o = 16; o; o >>= 1) {
        sre += __shfl_xor_sync(0xffffffffu, sre, o);
        sim += __shfl_xor_sync(0xffffffffu, sim, o);
    }
    float mr = sre * (1.f / SEQT), mi = sim * (1.f / SEQT);
    float mn = sqrtf(mr * mr + mi * mi);

    float cs[32]; float mx = -1e30f;
#pragma unroll
    for (int j = 0; j < 32; j++) {
        float dot = re[j] * mr + im[j] * mi;
        float nrm = sqrtf(re[j] * re[j] + im[j] * im[j]) * mn + 1e-8f;
        cs[j] = dot / nrm;
        mx = fmaxf(mx, cs[j]);
    }
#pragma unroll
    for (int o = 16; o; o >>= 1) mx = fmaxf(mx, __shfl_xor_sync(0xffffffffu, mx, o));
    float s = 0.f;
#pragma unroll
    for (int j = 0; j < 32; j++) { cs[j] = __expf(cs[j] - mx); s += cs[j]; }
#pragma unroll
    for (int o = 16; o; o >>= 1) s += __shfl_xor_sync(0xffffffffu, s, o);
    float inv = 1.f / s;

#pragma unroll
    for (int j = 0; j < 32; j++) {
        int t = lane + j * 32;
        float g = cs[j] * inv;
        gate[(long)bh * (SEQT * DHEAD) + t * DHEAD + d] = g;
        float v = proj[((long)(b * SEQT + t)) * 5120 + 4096 + h * DHEAD + d];
        float pv = g * v;
        __nv_bfloat16 hh = bf_hi(pv);
        long po = ((long)(b * SEQT + t)) * DMODEL + h * DHEAD + d;
        Ph[po] = hh; Pl[po] = bf_lo(pv, hh);
    }
}

// -----------------------------------------------------------------------------
extern "C" void kernel_launch(void* const* d_in, const int* in_sizes, int n_in,
                              void* d_out, int out_size)
{
    const float* x   = (const float*)d_in[0];
    const float* WQ  = (const float*)d_in[1];
    const float* WK  = (const float*)d_in[2];
    const float* Wre = (const float*)d_in[3];
    const float* Wim = (const float*)d_in[4];
    const float* WV  = (const float*)d_in[5];
    const float* WO  = (const float*)d_in[6];
    const float* lam = (const float*)d_in[7];
    float* out = (float*)d_out;

    float *pproj, *pS, *pDT, *pGateScr;
    __nv_bfloat16 *pxh, *pxl, *pW5h, *pW5l, *pWOh, *pWOl;
    __nv_bfloat16 *pQh, *pQl, *pKh, *pKl, *pAh, *pAl, *pDTh, *pDTl, *pPh, *pPl;
    cudaGetSymbolAddress((void**)&pproj, g_proj);
    cudaGetSymbolAddress((void**)&pS, g_S);
    cudaGetSymbolAddress((void**)&pDT, g_DT);
    cudaGetSymbolAddress((void**)&pGateScr, g_gate_scratch);
    cudaGetSymbolAddress((void**)&pxh, g_xh);
    cudaGetSymbolAddress((void**)&pxl, g_xl);
    cudaGetSymbolAddress((void**)&pW5h, g_W5h);
    cudaGetSymbolAddress((void**)&pW5l, g_W5l);
    cudaGetSymbolAddress((void**)&pWOh, g_WOh);
    cudaGetSymbolAddress((void**)&pWOl, g_WOl);
    cudaGetSymbolAddress((void**)&pQh, g_Qh);
    cudaGetSymbolAddress((void**)&pQl, g_Ql);
    cudaGetSymbolAddress((void**)&pKh, g_Kh);
    cudaGetSymbolAddress((void**)&pKl, g_Kl);
    cudaGetSymbolAddress((void**)&pAh, g_Ah);
    cudaGetSymbolAddress((void**)&pAl, g_Al);
    cudaGetSymbolAddress((void**)&pDTh, g_DTh);
    cudaGetSymbolAddress((void**)&pDTl, g_DTl);
    cudaGetSymbolAddress((void**)&pPh, g_Ph);
    cudaGetSymbolAddress((void**)&pPl, g_Pl);

    const long OUT_ELEMS  = (long)BT * DMODEL;
    const long GATE_ELEMS = (long)HEADEL;
    float* gate = (out_size >= (int)(OUT_ELEMS + GATE_ELEMS)) ? (out + OUT_ELEMS) : pGateScr;

    // 3 stages x (512+512 chunks) x hi/lo x 16B = 96 KB
    const int SMEM = 3 * (128 * 4 + 128 * 4) * 2 * 16;
    cudaFuncSetAttribute(mma_gemm<128,128,64,32,0,3>, cudaFuncAttributeMaxDynamicSharedMemorySize, SMEM);
    cudaFuncSetAttribute(mma_gemm<128,128,64,32,1,3>, cudaFuncAttributeMaxDynamicSharedMemorySize, SMEM);

    // ---- input splits ----
    split_ew_k<<<(BT * DMODEL + 255) / 256, 256>>>(x, pxh, pxl, BT * DMODEL);
    dim3 tb(32, 8), tg(32, 32);
    const float* Ws[5] = {WQ, WK, Wre, Wim, WV};
    for (int w = 0; w < 5; w++)
        splitT_w_k<<<tg, tb>>>(Ws[w], pW5h + (long)w * DMODEL * DMODEL, pW5l + (long)w * DMODEL * DMODEL);
    splitT_w_k<<<tg, tb>>>(WO, pWOh, pWOl);

    // ---- fused 5-way projection: [4096,5120] = x @ [WQ|WK|Wre|Wim|WV] ----
    mma_gemm<128,128,64,32,0,3><<<dim3(5120/128, BT/128, 1), 256, SMEM>>>(
        pxh, pxl, 0, DMODEL, pW5h, pW5l, 0, DMODEL,
        pproj, 0, 5120, nullptr, 0, nullptr, nullptr, DMODEL, 1.f, nullptr);

    // ---- per-head splits of Q, K; fused transposed split of Dre/Dim ----
    split_heads_k<<<HEADEL / 256, 256>>>(pproj, 0,    pQh, pQl);
    split_heads_k<<<HEADEL / 256, 256>>>(pproj, 1024, pKh, pKl);
    split_D_init_k<<<dim3(32, 2, NBH), tb>>>(pproj, 2048, 0,  pDT, pDTh, pDTl);
    split_D_init_k<<<dim3(32, 2, NBH), tb>>>(pproj, 3072, 64, pDT, pDTh, pDTl);

    // ---- scores: S[bh][t][s] = Q @ K^T / 8 ----
    mma_gemm<128,128,64,32,0,3><<<dim3(8, 8, NBH), 256, SMEM>>>(
        pQh, pQl, (long)SEQT * DHEAD, DHEAD,
        pKh, pKl, (long)SEQT * DHEAD, DHEAD,
        pS, (long)SEQT * SEQT, SEQT, nullptr, 0, nullptr, nullptr, DHEAD, 0.125f, nullptr);

    // ---- softmax rows -> A bf16 hi/lo (single pass) ----
    softmax_split_k<<<NBH * SEQT, 256>>>(pS, pAh, pAl);

    // ---- propagation, re/im fused M=128: F' = lam*(F @ A^T) + (1-lam)*F ----
    for (int s = 0; s < NSTEPS; s++) {
        long iin = (long)(s & 1) * FEL;
        long iou = (long)(1 - (s & 1)) * FEL;
        mma_gemm<128,128,64,32,1,3><<<dim3(8, 1, NBH), 256, SMEM>>>(
            pDTh + iin, pDTl + iin, 128L * SEQT, SEQT,
            pAh, pAl, (long)SEQT * SEQT, SEQT,
            pDT + iou, 128L * SEQT, SEQT,
            pDT + iin, 128L * SEQT,
            pDTh + iou, pDTl + iou,
            SEQT, 0.f, lam);
    }
    // after 3 steps final is pp index 1

    // ---- readout + gating (writes gate + P hi/lo) ----
    readout2_k<<<NBH * DHEAD / 8, 256>>>(pDT + FEL, pproj, gate, pPh, pPl);

    // ---- out = P @ W_O ----
    mma_gemm<128,128,64,32,0,3><<<dim3(DMODEL/128, BT/128, 1), 256, SMEM>>>(
        pPh, pPl, 0, DMODEL, pWOh, pWOl, 0, DMODEL,
        out, 0, DMODEL, nullptr, 0, nullptr, nullptr, DMODEL, 1.f, nullptr);
}